// round 6
// baseline (speedup 1.0000x reference)
#include <cuda_runtime.h>
#include <cstdint>
#include <math.h>

// DAGMixer R6: async-copy-engine pipelined version (R5 + warpsum race fix).
//   logits[row] = dot(orig[row], W[0:H]) + dot(dag[row], W[H:2H]) + b
//   gate = sigmoid(logits); mixed[row] = orig + gate*(dag - orig)
//
// 456 persistent CTAs (152 SM x 3), 256 threads. Reads driven by
// cp.async.bulk (UBLKCP) into a 4-stage smem ring with mbarrier completion —
// the copy engine keeps the HBM read stream busy independent of the SM's
// reduce/barrier/store phases. Each row is read from smem into registers
// once (used for both dot and mix). W register-resident. One __syncthreads
// per row. warpsum is parity double-buffered (j&1): with a single barrier
// per iteration warp skew is <1 iteration, so 2 buffers are sufficient and
// necessary (R5 failed with 1).

#define THREADS     256
#define H_DIM       2048
#define ROW_F4      (H_DIM / 4)          // 512 float4 per row
#define V4          2                    // ROW_F4 / THREADS
#define NWARP       (THREADS / 32)
#define STAGES      4
#define ROW_BYTES   (H_DIM * 4)          // 8192
#define STAGE_BYTES (2 * ROW_BYTES)      // orig + dag = 16384
#define GRID_CTAS   456                  // 152 SMs * 3
#define SMEM_DATA   (STAGES * STAGE_BYTES)           // 65536
#define SMEM_MBAR   SMEM_DATA                        // STAGES mbarriers, 8B each
#define SMEM_WSUM   (SMEM_MBAR + STAGES * 8)         // 2*NWARP floats
#define SMEM_TOTAL  (SMEM_WSUM + 2 * NWARP * 4 + 32)

__device__ __forceinline__ uint32_t smem_u32(const void* p) {
    uint32_t a;
    asm("{ .reg .u64 t; cvta.to.shared.u64 t, %1; cvt.u32.u64 %0, t; }"
        : "=r"(a) : "l"(p));
    return a;
}

__device__ __forceinline__ void mbar_init(uint32_t mbar, uint32_t count) {
    asm volatile("mbarrier.init.shared.b64 [%0], %1;" :: "r"(mbar), "r"(count) : "memory");
}

__device__ __forceinline__ void mbar_wait(uint32_t mbar, uint32_t phase) {
    asm volatile(
        "{\n\t"
        ".reg .pred P;\n\t"
        "W%=:\n\t"
        "mbarrier.try_wait.parity.acquire.cta.shared::cta.b64 P, [%0], %1, 0x989680;\n\t"
        "@P bra D%=;\n\t"
        "bra W%=;\n\t"
        "D%=:\n\t"
        "}"
        :: "r"(mbar), "r"(phase) : "memory");
}

// Issue both bulk copies (orig row + dag row) for one stage; completion
// accumulates STAGE_BYTES of tx on the stage's mbarrier.
__device__ __forceinline__ void issue_stage(uint32_t smem_base, uint32_t mbar_base,
                                            int stage,
                                            const float* o_src, const float* d_src)
{
    const uint32_t mbar = mbar_base + stage * 8;
    const uint32_t dst  = smem_base + stage * STAGE_BYTES;
    asm volatile("mbarrier.arrive.expect_tx.shared.b64 _, [%0], %1;"
                 :: "r"(mbar), "r"((uint32_t)STAGE_BYTES) : "memory");
    asm volatile("cp.async.bulk.shared::cta.global.mbarrier::complete_tx::bytes "
                 "[%0], [%1], %2, [%3];"
                 :: "r"(dst), "l"(o_src), "r"((uint32_t)ROW_BYTES), "r"(mbar) : "memory");
    asm volatile("cp.async.bulk.shared::cta.global.mbarrier::complete_tx::bytes "
                 "[%0], [%1], %2, [%3];"
                 :: "r"(dst + (uint32_t)ROW_BYTES), "l"(d_src),
                    "r"((uint32_t)ROW_BYTES), "r"(mbar) : "memory");
}

__global__ void dagmixer_kernel(const float* __restrict__ orig,
                                const float* __restrict__ dag,
                                const float* __restrict__ w,      // [2H]
                                const float* __restrict__ bgate,  // [1]
                                float* __restrict__ mixed,        // [rows*H]
                                float* __restrict__ gate_out,     // [rows]
                                int rows)
{
    extern __shared__ char smem[];
    const uint32_t smem_base = smem_u32(smem);
    const uint32_t mbar_base = smem_base + SMEM_MBAR;
    float* warpsum = (float*)(smem + SMEM_WSUM);   // [2][NWARP], parity buffered

    const int tid  = threadIdx.x;
    const int lane = tid & 31;
    const int wid  = tid >> 5;

    const int row0   = blockIdx.x;
    const int stride = gridDim.x;
    if (row0 >= rows) return;
    const int n_iters = (rows - row0 + stride - 1) / stride;

    // Init stage mbarriers (single arrival each: the producer's expect_tx).
    if (tid == 0) {
        #pragma unroll
        for (int s = 0; s < STAGES; s++) mbar_init(mbar_base + s * 8, 1);
        asm volatile("fence.proxy.async.shared::cta;" ::: "memory");
    }
    __syncthreads();

    // W slice in registers for the whole kernel.
    float4 wo[V4], wd[V4];
    #pragma unroll
    for (int k = 0; k < V4; k++) {
        wo[k] = ((const float4*)w)[tid + k * THREADS];
        wd[k] = ((const float4*)(w + H_DIM))[tid + k * THREADS];
    }
    const float bias = bgate[0];

    // Prefill STAGES-1 stages.
    if (tid == 0) {
        const int npre = (STAGES - 1 < n_iters) ? STAGES - 1 : n_iters;
        for (int j = 0; j < npre; j++) {
            const size_t r = (size_t)row0 + (size_t)j * stride;
            issue_stage(smem_base, mbar_base, j,
                        orig + r * H_DIM, dag + r * H_DIM);
        }
    }

    int s = 0, ph = 0;
    for (int j = 0; j < n_iters; j++) {
        const size_t row = (size_t)row0 + (size_t)j * stride;
        const int    wp  = j & 1;          // warpsum parity buffer

        mbar_wait(mbar_base + s * 8, (uint32_t)ph);

        // Read this row from smem into registers (used for dot AND mix).
        const float4* so = (const float4*)(smem + (size_t)s * STAGE_BYTES);
        const float4* sd = (const float4*)(smem + (size_t)s * STAGE_BYTES + ROW_BYTES);
        float4 ov[V4], dv[V4];
        #pragma unroll
        for (int k = 0; k < V4; k++) {
            ov[k] = so[tid + k * THREADS];
            dv[k] = sd[tid + k * THREADS];
        }

        // Partial dot against register-resident W.
        float partial = 0.0f;
        #pragma unroll
        for (int k = 0; k < V4; k++) {
            partial = fmaf(ov[k].x, wo[k].x, partial);
            partial = fmaf(ov[k].y, wo[k].y, partial);
            partial = fmaf(ov[k].z, wo[k].z, partial);
            partial = fmaf(ov[k].w, wo[k].w, partial);
            partial = fmaf(dv[k].x, wd[k].x, partial);
            partial = fmaf(dv[k].y, wd[k].y, partial);
            partial = fmaf(dv[k].z, wd[k].z, partial);
            partial = fmaf(dv[k].w, wd[k].w, partial);
        }
        #pragma unroll
        for (int off = 16; off > 0; off >>= 1)
            partial += __shfl_xor_sync(0xffffffff, partial, off);
        if (lane == 0) warpsum[wp * NWARP + wid] = partial;

        // Single barrier: publishes warpsum[wp] AND certifies this stage
        // fully consumed (row data now in registers).
        __syncthreads();

        // Refill: iteration j+STAGES-1 goes into stage (s+STAGES-1)%STAGES,
        // consumed at iteration j-1 (or never used, at j=0).
        if (tid == 0) {
            const int jn = j + STAGES - 1;
            if (jn < n_iters) {
                const size_t rn = (size_t)row0 + (size_t)jn * stride;
                issue_stage(smem_base, mbar_base, (s + STAGES - 1) % STAGES,
                            orig + rn * H_DIM, dag + rn * H_DIM);
            }
        }

        float acc = bias;
        #pragma unroll
        for (int i = 0; i < NWARP; i++) acc += warpsum[wp * NWARP + i];
        const float g = 1.0f / (1.0f + __expf(-acc));
        if (tid == 0) gate_out[row] = g;

        // Mix from registers, store.
        float4* pm = (float4*)mixed + row * ROW_F4 + tid;
        #pragma unroll
        for (int k = 0; k < V4; k++) {
            float4 r;
            r.x = fmaf(g, dv[k].x - ov[k].x, ov[k].x);
            r.y = fmaf(g, dv[k].y - ov[k].y, ov[k].y);
            r.z = fmaf(g, dv[k].z - ov[k].z, ov[k].z);
            r.w = fmaf(g, dv[k].w - ov[k].w, ov[k].w);
            pm[k * THREADS] = r;
        }

        if (++s == STAGES) { s = 0; ph ^= 1; }
    }
}

extern "C" void kernel_launch(void* const* d_in, const int* in_sizes, int n_in,
                              void* d_out, int out_size)
{
    const float* orig  = (const float*)d_in[0];  // original_hidden [B,T,H]
    const float* dag   = (const float*)d_in[1];  // dag_hidden      [B,T,H]
    const float* wgate = (const float*)d_in[2];  // W_gate          [2H,1]
    const float* bgate = (const float*)d_in[3];  // b_gate          [1]

    const int total = in_sizes[0];               // B*T*H
    const int rows  = total / H_DIM;             // B*T

    float* mixed    = (float*)d_out;
    float* gate_out = (float*)d_out + total;

    cudaFuncSetAttribute(dagmixer_kernel,
                         cudaFuncAttributeMaxDynamicSharedMemorySize, SMEM_TOTAL);

    const int grid = (rows < GRID_CTAS) ? rows : GRID_CTAS;
    dagmixer_kernel<<<grid, THREADS, SMEM_TOTAL>>>(orig, dag, wgate, bgate,
                                                   mixed, gate_out, rows);
}

// round 8
// speedup vs baseline: 1.0189x; 1.0189x over previous
#include <cuda_runtime.h>
#include <math.h>

// DAGMixer R7: R1 baseline (best bench: 62.3us) minus removable overheads.
//   logits[row] = dot(orig[row], W[0:H]) + dot(dag[row], W[H:2H]) + b
//   gate = sigmoid(logits); mixed[row] = orig + gate*(dag - orig)
// rows = B*T = 16384, H = 2048 (fp32).
//
// One CTA per row (16384 short CTAs — the work distributor rebalances,
// which empirically beats persistent CTAs on replay-timed bench), 256
// threads, 8 CTAs/SM. Each thread holds its 8 orig + 8 dag floats in
// registers across the reduce so every HBM byte is touched once.
// R7 vs R1: single __syncthreads (redundant warpsum sum in all threads
// instead of a tid0-compute + second barrier), __expf sigmoid.

#define THREADS 256
#define H_DIM 2048
#define V4_PER_THREAD 2   // (H_DIM/4) / THREADS
#define NWARP (THREADS / 32)

__global__ __launch_bounds__(THREADS, 8)
void dagmixer_kernel(const float* __restrict__ orig,
                     const float* __restrict__ dag,
                     const float* __restrict__ w,     // [2H]: W_o then W_d
                     const float* __restrict__ bgate, // [1]
                     float* __restrict__ mixed,       // [rows*H]
                     float* __restrict__ gate_out)    // [rows]
{
    const int row = blockIdx.x;
    const int tid = threadIdx.x;

    const float4* __restrict__ o4  = (const float4*)(orig + (size_t)row * H_DIM);
    const float4* __restrict__ d4  = (const float4*)(dag  + (size_t)row * H_DIM);
    const float4* __restrict__ wo4 = (const float4*)(w);
    const float4* __restrict__ wd4 = (const float4*)(w + H_DIM);

    float4 ov[V4_PER_THREAD];
    float4 dv[V4_PER_THREAD];
    float partial = 0.0f;

    #pragma unroll
    for (int k = 0; k < V4_PER_THREAD; k++) {
        const int idx = tid + k * THREADS;   // float4 index, coalesced
        ov[k] = o4[idx];
        dv[k] = d4[idx];
        const float4 a = wo4[idx];
        const float4 c = wd4[idx];
        partial += ov[k].x * a.x + ov[k].y * a.y + ov[k].z * a.z + ov[k].w * a.w;
        partial += dv[k].x * c.x + dv[k].y * c.y + dv[k].z * c.z + dv[k].w * c.w;
    }

    // Warp reduce.
    #pragma unroll
    for (int off = 16; off > 0; off >>= 1)
        partial += __shfl_xor_sync(0xffffffff, partial, off);

    __shared__ float warpsum[NWARP];
    const int wid  = tid >> 5;
    const int lane = tid & 31;
    if (lane == 0) warpsum[wid] = partial;
    __syncthreads();   // single barrier: publishes all warpsums

    // All threads redundantly finish the reduce + sigmoid (no 2nd barrier).
    float s = bgate[0];
    #pragma unroll
    for (int i = 0; i < NWARP; i++) s += warpsum[i];
    const float g = 1.0f / (1.0f + __expf(-s));
    if (tid == 0) gate_out[row] = g;

    // Mix from registers and store.
    float4* __restrict__ m4 = (float4*)(mixed + (size_t)row * H_DIM);
    #pragma unroll
    for (int k = 0; k < V4_PER_THREAD; k++) {
        const int idx = tid + k * THREADS;
        float4 r;
        r.x = fmaf(g, dv[k].x - ov[k].x, ov[k].x);
        r.y = fmaf(g, dv[k].y - ov[k].y, ov[k].y);
        r.z = fmaf(g, dv[k].z - ov[k].z, ov[k].z);
        r.w = fmaf(g, dv[k].w - ov[k].w, ov[k].w);
        m4[idx] = r;
    }
}

extern "C" void kernel_launch(void* const* d_in, const int* in_sizes, int n_in,
                              void* d_out, int out_size)
{
    const float* orig  = (const float*)d_in[0];  // original_hidden [B,T,H]
    const float* dag   = (const float*)d_in[1];  // dag_hidden      [B,T,H]
    const float* wgate = (const float*)d_in[2];  // W_gate          [2H,1]
    const float* bgate = (const float*)d_in[3];  // b_gate          [1]

    const int total = in_sizes[0];               // B*T*H
    const int rows  = total / H_DIM;             // B*T

    float* mixed    = (float*)d_out;             // first B*T*H floats
    float* gate_out = (float*)d_out + total;     // then B*T gate values

    dagmixer_kernel<<<rows, THREADS>>>(orig, dag, wgate, bgate, mixed, gate_out);
}

// round 9
// speedup vs baseline: 1.0868x; 1.0667x over previous
#include <cuda_runtime.h>
#include <math.h>

// DAGMixer R9: exact R1 structure (best bench: 62.3us), single tweak:
// __expf in the tid0-only sigmoid.
//   logits[row] = dot(orig[row], W[0:H]) + dot(dag[row], W[H:2H]) + b
//   gate = sigmoid(logits); mixed[row] = orig + gate*(dag - orig)
// rows = B*T = 16384, H = 2048 (fp32).
//
// One CTA per row, 256 threads, 8 CTAs/SM. Each thread holds its 8 orig +
// 8 dag floats in registers across the reduce so every HBM byte is touched
// once. Two barriers with tid0-only final reduce: keeps all other warps'
// load->store path free of reduce compute (R7 showed the all-threads
// redundant variant lengthens the critical path and costs ~6% DRAM).

#define THREADS 256
#define H_DIM 2048
#define V4_PER_THREAD 2   // (H_DIM/4) / THREADS = 512/256

__global__ __launch_bounds__(THREADS, 8)
void dagmixer_kernel(const float* __restrict__ orig,
                     const float* __restrict__ dag,
                     const float* __restrict__ w,     // [2H]: W_o then W_d
                     const float* __restrict__ bgate, // [1]
                     float* __restrict__ mixed,       // [rows*H]
                     float* __restrict__ gate_out)    // [rows]
{
    const int row = blockIdx.x;
    const int tid = threadIdx.x;

    const float4* __restrict__ o4  = (const float4*)(orig + (size_t)row * H_DIM);
    const float4* __restrict__ d4  = (const float4*)(dag  + (size_t)row * H_DIM);
    const float4* __restrict__ wo4 = (const float4*)(w);
    const float4* __restrict__ wd4 = (const float4*)(w + H_DIM);

    float4 ov[V4_PER_THREAD];
    float4 dv[V4_PER_THREAD];
    float partial = 0.0f;

    #pragma unroll
    for (int k = 0; k < V4_PER_THREAD; k++) {
        const int idx = tid + k * THREADS;   // float4 index, coalesced
        ov[k] = o4[idx];
        dv[k] = d4[idx];
        const float4 a = wo4[idx];
        const float4 c = wd4[idx];
        partial += ov[k].x * a.x + ov[k].y * a.y + ov[k].z * a.z + ov[k].w * a.w;
        partial += dv[k].x * c.x + dv[k].y * c.y + dv[k].z * c.z + dv[k].w * c.w;
    }

    // Warp reduce
    #pragma unroll
    for (int off = 16; off > 0; off >>= 1)
        partial += __shfl_xor_sync(0xffffffff, partial, off);

    __shared__ float warpsum[THREADS / 32];
    __shared__ float gate_sh;
    const int wid  = tid >> 5;
    const int lane = tid & 31;
    if (lane == 0) warpsum[wid] = partial;
    __syncthreads();

    if (tid == 0) {
        float s = bgate[0];
        #pragma unroll
        for (int i = 0; i < THREADS / 32; i++) s += warpsum[i];
        const float g = 1.0f / (1.0f + __expf(-s));
        gate_sh = g;
        gate_out[row] = g;
    }
    __syncthreads();

    const float g = gate_sh;
    float4* __restrict__ m4 = (float4*)(mixed + (size_t)row * H_DIM);

    #pragma unroll
    for (int k = 0; k < V4_PER_THREAD; k++) {
        const int idx = tid + k * THREADS;
        float4 r;
        r.x = ov[k].x + g * (dv[k].x - ov[k].x);
        r.y = ov[k].y + g * (dv[k].y - ov[k].y);
        r.z = ov[k].z + g * (dv[k].z - ov[k].z);
        r.w = ov[k].w + g * (dv[k].w - ov[k].w);
        m4[idx] = r;
    }
}

extern "C" void kernel_launch(void* const* d_in, const int* in_sizes, int n_in,
                              void* d_out, int out_size)
{
    const float* orig  = (const float*)d_in[0];  // original_hidden [B,T,H]
    const float* dag   = (const float*)d_in[1];  // dag_hidden      [B,T,H]
    const float* wgate = (const float*)d_in[2];  // W_gate          [2H,1]
    const float* bgate = (const float*)d_in[3];  // b_gate          [1]

    const int total = in_sizes[0];               // B*T*H
    const int rows  = total / H_DIM;             // B*T

    float* mixed    = (float*)d_out;             // first B*T*H floats
    float* gate_out = (float*)d_out + total;     // then B*T gate values

    dagmixer_kernel<<<rows, THREADS>>>(orig, dag, wgate, bgate, mixed, gate_out);
}